// round 8
// baseline (speedup 1.0000x reference)
#include <cuda_runtime.h>
#include <cuda_fp16.h>
#include <stdint.h>

#define N_NODES   100000
#define N_EDGES   1200000
#define N_GRAPHS  128
#define D         64
#define N_CLASSES 10

#define SCAN_NB   ((N_NODES + 1023) / 1024)

// ---- device scratch (allocation-free) ----
__device__ __align__(128) unsigned g_hh[N_NODES * 32];   // GEMM out, half2-packed (128B/row)
__device__ __align__(128) float  g_agg[N_NODES * D];     // aggregated fp32 / next input
__device__ __align__(128) float  g_dinv[N_NODES];
__device__ __align__(128) int    g_deg[N_NODES];
__device__ __align__(128) int    g_off[N_NODES + 1];
__device__ __align__(128) int    g_cursor[N_NODES];
__device__ __align__(128) float2 g_edge[N_EDGES];        // {src_as_bits, norm}
__device__ __align__(128) int    g_bsum[SCAN_NB];
__device__ __align__(128) float  g_pool[N_GRAPHS * D];
__device__ int g_cnt[N_GRAPHS];
__device__ int g_ei64;
__device__ int g_bat64;

// ---------------------------------------------------------------------------
// f32x2 packed FMA helpers (sm_103a)
// ---------------------------------------------------------------------------
__device__ __forceinline__ void fma2(unsigned long long& d,
                                     unsigned long long a,
                                     unsigned long long b) {
    asm("fma.rn.f32x2 %0, %1, %2, %0;" : "+l"(d) : "l"(a), "l"(b));
}
__device__ __forceinline__ unsigned long long dupf(float a) {
    unsigned long long u;
    asm("mov.b64 %0, {%1, %1};" : "=l"(u) : "f"(a));
    return u;
}
__device__ __forceinline__ float2 unpack2(unsigned long long u) {
    float2 f;
    asm("mov.b64 {%0, %1}, %2;" : "=f"(f.x), "=f"(f.y) : "l"(u));
    return f;
}
__device__ __forceinline__ void red_add_v4(float* addr, float4 v) {
    asm volatile("red.global.add.v4.f32 [%0], {%1, %2, %3, %4};"
                 :: "l"(addr), "f"(v.x), "f"(v.y), "f"(v.z), "f"(v.w)
                 : "memory");
}

// ---------------------------------------------------------------------------
// dtype detection + zero-init of tiny accumulators
// ---------------------------------------------------------------------------
__global__ void detect_kernel(const int* ei_words, const int* bat_words) {
    int v = 0;
    for (int i = threadIdx.x; i < 2048; i += blockDim.x) v |= ei_words[2 * i + 1];
    int ei_nz = __syncthreads_or(v != 0);
    int w = 0;
    for (int i = threadIdx.x; i < 2048; i += blockDim.x) {
        int wi = N_NODES - 1 - 2 * i;
        wi -= (1 - (wi & 1));
        if (wi >= 1) w |= bat_words[wi];
    }
    int bat_nz = __syncthreads_or(w != 0);
    if (threadIdx.x == 0) { g_ei64 = ei_nz ? 0 : 1; g_bat64 = bat_nz ? 0 : 1; }
    if (threadIdx.x < N_GRAPHS) g_cnt[threadIdx.x] = 0;
    for (int i = threadIdx.x; i < N_GRAPHS * D; i += blockDim.x) g_pool[i] = 0.f;
}

__device__ __forceinline__ int load_ei(const void* p, long long i) {
    return g_ei64 ? (int)((const long long*)p)[i] : ((const int*)p)[i];
}
__device__ __forceinline__ int load_bat(const void* p, int i) {
    return g_bat64 ? (int)((const long long*)p)[i] : ((const int*)p)[i];
}

// ---------------------------------------------------------------------------
// degree histogram
// ---------------------------------------------------------------------------
__global__ void deg_kernel(const void* ei) {
    int e = blockIdx.x * blockDim.x + threadIdx.x;
    if (e >= N_EDGES) return;
    atomicAdd(&g_deg[load_ei(ei, (long long)N_EDGES + e)], 1);
}

// ---------------------------------------------------------------------------
// scan1: per-block (1024-item) sums of g_deg
// ---------------------------------------------------------------------------
__global__ void scan1_kernel() {
    __shared__ int s[256];
    int t = threadIdx.x;
    int base = blockIdx.x * 1024 + t * 4;
    int sum = 0;
    #pragma unroll
    for (int j = 0; j < 4; j++) { int i = base + j; if (i < N_NODES) sum += g_deg[i]; }
    s[t] = sum; __syncthreads();
    for (int o = 128; o > 0; o >>= 1) { if (t < o) s[t] += s[t + o]; __syncthreads(); }
    if (t == 0) g_bsum[blockIdx.x] = s[0];
}

// ---------------------------------------------------------------------------
// scan3 (fused): re-scan the 98 block sums in smem (kills scan2), produce
// g_off/g_cursor, and fold in dinv + per-graph node counts.
// ---------------------------------------------------------------------------
__global__ void scan3_kernel(const void* __restrict__ batch) {
    __shared__ int sb[128];
    __shared__ int ts[256];
    int t = threadIdx.x;

    if (t < 128) sb[t] = (t < SCAN_NB) ? g_bsum[t] : 0;
    __syncthreads();
    for (int o = 1; o < 128; o <<= 1) {
        int v = (t < 128 && t >= o) ? sb[t - o] : 0;
        __syncthreads();
        if (t < 128) sb[t] += v;
        __syncthreads();
    }
    int blockpre = (blockIdx.x == 0) ? 0 : sb[blockIdx.x - 1];

    int base = blockIdx.x * 1024 + t * 4;
    int v[4];
    #pragma unroll
    for (int j = 0; j < 4; j++) v[j] = (base + j < N_NODES) ? g_deg[base + j] : 0;
    ts[t] = v[0] + v[1] + v[2] + v[3]; __syncthreads();
    for (int o = 1; o < 256; o <<= 1) {
        int x = (t >= o) ? ts[t - o] : 0;
        __syncthreads(); ts[t] += x; __syncthreads();
    }
    int pre = blockpre + ((t == 0) ? 0 : ts[t - 1]);
    #pragma unroll
    for (int j = 0; j < 4; j++) {
        int i = base + j;
        if (i < N_NODES) {
            g_off[i] = pre; g_cursor[i] = pre;
            g_dinv[i] = rsqrtf((float)v[j] + 1.0f);
            atomicAdd(&g_cnt[load_bat(batch, i)], 1);   // warp-uniform -> REDUX
        }
        pre += v[j];
    }
    if (blockIdx.x == 0 && t == 0) g_off[N_NODES] = N_EDGES;
}

// CSR fill: payload = {src row bits, norm = dinv[r]*dinv[c]}
__global__ void fill_kernel(const void* __restrict__ ei) {
    int e = blockIdx.x * blockDim.x + threadIdx.x;
    if (e >= N_EDGES) return;
    int r = load_ei(ei, e);
    int c = load_ei(ei, (long long)N_EDGES + e);
    int pos = atomicAdd(&g_cursor[c], 1);
    g_edge[pos] = make_float2(__int_as_float(r), g_dinv[r] * g_dinv[c]);
}

// ---------------------------------------------------------------------------
// GEMM: g_hh(half) = (relu? relu(A):A) @ W.  64-row tiles, 128 thr/block.
// ---------------------------------------------------------------------------
#define SA_STRIDE 66
__global__ __launch_bounds__(128) void gemm_kernel(const float* __restrict__ A,
                                                   const float* __restrict__ W,
                                                   int relu_in) {
    __shared__ float sA[64 * SA_STRIDE];
    __shared__ float sW[64 * 64];
    const int t = threadIdx.x;
    const int base = blockIdx.x * 64;

    for (int i = t; i < 1024; i += 128)
        ((float4*)sW)[i] = ((const float4*)W)[i];

    for (int i = t; i < 1024; i += 128) {
        int row = i >> 4, quad = i & 15;
        int gr = base + row;
        float4 v = make_float4(0.f, 0.f, 0.f, 0.f);
        if (gr < N_NODES) v = ((const float4*)A)[gr * 16 + quad];
        if (relu_in) {
            v.x = fmaxf(v.x, 0.f); v.y = fmaxf(v.y, 0.f);
            v.z = fmaxf(v.z, 0.f); v.w = fmaxf(v.w, 0.f);
        }
        float* dst = sA + row * SA_STRIDE + quad * 4;
        dst[0] = v.x; dst[1] = v.y; dst[2] = v.z; dst[3] = v.w;
    }
    __syncthreads();

    const int q2  = t & 7;
    const int grp = t >> 3;
    unsigned long long acc[4][4];
    #pragma unroll
    for (int r = 0; r < 4; r++)
        #pragma unroll
        for (int p = 0; p < 4; p++) acc[r][p] = 0ull;

    const float* wbase = sW + q2 * 8;
    const float* abase = sA + grp * 4 * SA_STRIDE;

    #pragma unroll 8
    for (int k = 0; k < 64; k++) {
        const float* wr = wbase + k * 64;
        unsigned long long w0 = *(const unsigned long long*)(wr + 0);
        unsigned long long w1 = *(const unsigned long long*)(wr + 2);
        unsigned long long w2 = *(const unsigned long long*)(wr + 4);
        unsigned long long w3 = *(const unsigned long long*)(wr + 6);
        #pragma unroll
        for (int r = 0; r < 4; r++) {
            unsigned long long a2 = dupf(abase[r * SA_STRIDE + k]);
            fma2(acc[r][0], a2, w0);
            fma2(acc[r][1], a2, w1);
            fma2(acc[r][2], a2, w2);
            fma2(acc[r][3], a2, w3);
        }
    }

    #pragma unroll
    for (int r = 0; r < 4; r++) {
        int gr = base + grp * 4 + r;
        if (gr >= N_NODES) continue;
        half2 h0 = __float22half2_rn(unpack2(acc[r][0]));
        half2 h1 = __float22half2_rn(unpack2(acc[r][1]));
        half2 h2 = __float22half2_rn(unpack2(acc[r][2]));
        half2 h3 = __float22half2_rn(unpack2(acc[r][3]));
        uint4 u;
        u.x = *(unsigned*)&h0; u.y = *(unsigned*)&h1;
        u.z = *(unsigned*)&h2; u.w = *(unsigned*)&h3;
        ((uint4*)g_hh)[gr * 8 + q2] = u;
    }
}

// ---------------------------------------------------------------------------
// CSR aggregation: 16 threads/node, fp16 gathers, unroll-4 for MLP.
// ---------------------------------------------------------------------------
__device__ __forceinline__ void acc4h(float* a, uint2 u, float n) {
    float2 f0 = __half22float2(*(half2*)&u.x);
    float2 f1 = __half22float2(*(half2*)&u.y);
    a[0] += f0.x * n; a[1] += f0.y * n;
    a[2] += f1.x * n; a[3] += f1.y * n;
}

__global__ __launch_bounds__(256) void agg_kernel(const float* __restrict__ bias,
                                                  const void* __restrict__ batch,
                                                  int to_pool) {
    int gid = blockIdx.x * blockDim.x + threadIdx.x;
    if (gid >= N_NODES * 16) return;
    int node = gid >> 4, q = gid & 15;
    int j   = g_off[node];
    int end = g_off[node + 1];
    const uint2* h = (const uint2*)g_hh;    // 16 uint2 per row

    float a[4] = {0.f, 0.f, 0.f, 0.f};
    for (; j + 4 <= end; j += 4) {
        float2 e0 = g_edge[j],     e1 = g_edge[j + 1];
        float2 e2 = g_edge[j + 2], e3 = g_edge[j + 3];
        uint2 u0 = h[(__float_as_int(e0.x) << 4) + q];
        uint2 u1 = h[(__float_as_int(e1.x) << 4) + q];
        uint2 u2 = h[(__float_as_int(e2.x) << 4) + q];
        uint2 u3 = h[(__float_as_int(e3.x) << 4) + q];
        acc4h(a, u0, e0.y);
        acc4h(a, u1, e1.y);
        acc4h(a, u2, e2.y);
        acc4h(a, u3, e3.y);
    }
    for (; j < end; j++) {
        float2 e0 = g_edge[j];
        acc4h(a, h[(__float_as_int(e0.x) << 4) + q], e0.y);
    }
    // self loop + bias
    float di = g_dinv[node];
    acc4h(a, h[(node << 4) + q], di * di);
    float4 b = ((const float4*)bias)[q];
    a[0] += b.x; a[1] += b.y; a[2] += b.z; a[3] += b.w;

    if (to_pool) {
        int bg = load_bat(batch, node);
        red_add_v4(&g_pool[bg * D + q * 4], make_float4(a[0], a[1], a[2], a[3]));
    } else {
        ((float4*)g_agg)[gid] = make_float4(a[0], a[1], a[2], a[3]);
    }
}

__global__ void final_kernel(const float* __restrict__ linW,
                             const float* __restrict__ linb,
                             float* __restrict__ out) {
    int id = blockIdx.x * blockDim.x + threadIdx.x;
    if (id >= N_GRAPHS * N_CLASSES) return;
    int b = id / N_CLASSES, c = id % N_CLASSES;
    float inv = 1.0f / fmaxf((float)g_cnt[b], 1.0f);
    float acc = linb[c];
    #pragma unroll
    for (int d = 0; d < D; d++)
        acc += (g_pool[b * D + d] * inv) * linW[d * N_CLASSES + c];
    out[id] = acc;
}

extern "C" void kernel_launch(void* const* d_in, const int* in_sizes, int n_in,
                              void* d_out, int out_size) {
    const float* x    = (const float*)d_in[0];
    const void*  ei   = d_in[1];
    const void*  bat  = d_in[2];
    const float* W1   = (const float*)d_in[3];
    const float* b1   = (const float*)d_in[4];
    const float* W2   = (const float*)d_in[5];
    const float* b2   = (const float*)d_in[6];
    const float* W3   = (const float*)d_in[7];
    const float* b3   = (const float*)d_in[8];
    const float* linW = (const float*)d_in[9];
    const float* linb = (const float*)d_in[10];
    float* out = (float*)d_out;

    void *deg_p, *agg_p;
    cudaGetSymbolAddress(&deg_p, g_deg);
    cudaGetSymbolAddress(&agg_p, g_agg);
    const float* agg = (const float*)agg_p;

    cudaMemsetAsync(deg_p, 0, N_NODES * sizeof(int));

    detect_kernel<<<1, 256>>>((const int*)ei, (const int*)bat);
    deg_kernel<<<(N_EDGES + 255) / 256, 256>>>(ei);
    scan1_kernel<<<SCAN_NB, 256>>>();
    scan3_kernel<<<SCAN_NB, 256>>>(bat);
    fill_kernel<<<(N_EDGES + 255) / 256, 256>>>(ei);

    const int GEMM_BLOCKS = (N_NODES + 63) / 64;
    const int NODE16      = (N_NODES * 16 + 255) / 256;

    gemm_kernel<<<GEMM_BLOCKS, 128>>>(x, W1, 0);
    agg_kernel<<<NODE16, 256>>>(b1, bat, 0);
    gemm_kernel<<<GEMM_BLOCKS, 128>>>(agg, W2, 1);
    agg_kernel<<<NODE16, 256>>>(b2, bat, 0);
    gemm_kernel<<<GEMM_BLOCKS, 128>>>(agg, W3, 1);
    agg_kernel<<<NODE16, 256>>>(b3, bat, 1);   // fused pool

    final_kernel<<<(N_GRAPHS * N_CLASSES + 255) / 256, 256>>>(linW, linb, out);
}

// round 9
// speedup vs baseline: 1.1676x; 1.1676x over previous
#include <cuda_runtime.h>
#include <cuda_fp16.h>
#include <stdint.h>

#define N_NODES   100000
#define N_EDGES   1200000
#define N_GRAPHS  128
#define D         64
#define N_CLASSES 10

#define SCAN_NB   ((N_NODES + 1023) / 1024)

// ---- device scratch (allocation-free) ----
__device__ __align__(128) unsigned g_hh[N_NODES * 32];   // GEMM out, half2-packed (128B/row)
__device__ __align__(128) float  g_agg[N_NODES * D];     // aggregated fp32 / next input
__device__ __align__(128) float  g_dinv[N_NODES];
__device__ __align__(128) int    g_deg[N_NODES];
__device__ __align__(128) int    g_off[N_NODES + 1];
__device__ __align__(128) int    g_cursor[N_NODES];
__device__ __align__(128) float2 g_edge[N_EDGES];        // {src_as_bits, norm}
__device__ __align__(128) int    g_bsum[SCAN_NB];
__device__ __align__(128) float  g_pool[N_GRAPHS * D];
__device__ int g_lb[N_GRAPHS + 1];                       // graph start offsets (sorted batch)
__device__ int g_ei64;
__device__ int g_bat64;

// ---------------------------------------------------------------------------
// f32x2 packed FMA helpers (sm_103a)
// ---------------------------------------------------------------------------
__device__ __forceinline__ void fma2(unsigned long long& d,
                                     unsigned long long a,
                                     unsigned long long b) {
    asm("fma.rn.f32x2 %0, %1, %2, %0;" : "+l"(d) : "l"(a), "l"(b));
}
__device__ __forceinline__ unsigned long long dupf(float a) {
    unsigned long long u;
    asm("mov.b64 %0, {%1, %1};" : "=l"(u) : "f"(a));
    return u;
}
__device__ __forceinline__ float2 unpack2(unsigned long long u) {
    float2 f;
    asm("mov.b64 {%0, %1}, %2;" : "=f"(f.x), "=f"(f.y) : "l"(u));
    return f;
}
__device__ __forceinline__ void red_add_v4(float* addr, float4 v) {
    asm volatile("red.global.add.v4.f32 [%0], {%1, %2, %3, %4};"
                 :: "l"(addr), "f"(v.x), "f"(v.y), "f"(v.z), "f"(v.w)
                 : "memory");
}

// ---------------------------------------------------------------------------
// dtype detection + zero-init of pool
// ---------------------------------------------------------------------------
__global__ void detect_kernel(const int* ei_words, const int* bat_words) {
    int v = 0;
    for (int i = threadIdx.x; i < 2048; i += blockDim.x) v |= ei_words[2 * i + 1];
    int ei_nz = __syncthreads_or(v != 0);
    int w = 0;
    for (int i = threadIdx.x; i < 2048; i += blockDim.x) {
        int wi = N_NODES - 1 - 2 * i;
        wi -= (1 - (wi & 1));
        if (wi >= 1) w |= bat_words[wi];
    }
    int bat_nz = __syncthreads_or(w != 0);
    if (threadIdx.x == 0) { g_ei64 = ei_nz ? 0 : 1; g_bat64 = bat_nz ? 0 : 1; }
    for (int i = threadIdx.x; i < N_GRAPHS * D; i += blockDim.x) g_pool[i] = 0.f;
}

__device__ __forceinline__ int load_ei(const void* p, long long i) {
    return g_ei64 ? (int)((const long long*)p)[i] : ((const int*)p)[i];
}
__device__ __forceinline__ int load_bat(const void* p, int i) {
    return g_bat64 ? (int)((const long long*)p)[i] : ((const int*)p)[i];
}

// ---------------------------------------------------------------------------
// degree histogram
// ---------------------------------------------------------------------------
__global__ void deg_kernel(const void* ei) {
    int e = blockIdx.x * blockDim.x + threadIdx.x;
    if (e >= N_EDGES) return;
    atomicAdd(&g_deg[load_ei(ei, (long long)N_EDGES + e)], 1);
}

// ---------------------------------------------------------------------------
// graph boundaries: sorted batch -> transition scan, zero atomics.
// ---------------------------------------------------------------------------
__global__ void lb_kernel(const void* __restrict__ batch) {
    int i = blockIdx.x * blockDim.x + threadIdx.x;
    if (i >= N_NODES) return;
    int b0 = load_bat(batch, i);
    if (i == 0)
        for (int b = 0; b <= b0; b++) g_lb[b] = 0;
    int b1 = (i + 1 < N_NODES) ? load_bat(batch, i + 1) : N_GRAPHS;
    for (int b = b0 + 1; b <= b1; b++) g_lb[b] = i + 1;
}

// ---------------------------------------------------------------------------
// scan1: per-block (1024-item) sums of g_deg
// ---------------------------------------------------------------------------
__global__ void scan1_kernel() {
    __shared__ int s[256];
    int t = threadIdx.x;
    int base = blockIdx.x * 1024 + t * 4;
    int sum = 0;
    #pragma unroll
    for (int j = 0; j < 4; j++) { int i = base + j; if (i < N_NODES) sum += g_deg[i]; }
    s[t] = sum; __syncthreads();
    for (int o = 128; o > 0; o >>= 1) { if (t < o) s[t] += s[t + o]; __syncthreads(); }
    if (t == 0) g_bsum[blockIdx.x] = s[0];
}

// ---------------------------------------------------------------------------
// scan3: rescan block sums in smem, emit g_off/g_cursor + dinv (no atomics).
// ---------------------------------------------------------------------------
__global__ void scan3_kernel() {
    __shared__ int sb[128];
    __shared__ int ts[256];
    int t = threadIdx.x;

    if (t < 128) sb[t] = (t < SCAN_NB) ? g_bsum[t] : 0;
    __syncthreads();
    for (int o = 1; o < 128; o <<= 1) {
        int v = (t < 128 && t >= o) ? sb[t - o] : 0;
        __syncthreads();
        if (t < 128) sb[t] += v;
        __syncthreads();
    }
    int blockpre = (blockIdx.x == 0) ? 0 : sb[blockIdx.x - 1];

    int base = blockIdx.x * 1024 + t * 4;
    int v[4];
    #pragma unroll
    for (int j = 0; j < 4; j++) v[j] = (base + j < N_NODES) ? g_deg[base + j] : 0;
    ts[t] = v[0] + v[1] + v[2] + v[3]; __syncthreads();
    for (int o = 1; o < 256; o <<= 1) {
        int x = (t >= o) ? ts[t - o] : 0;
        __syncthreads(); ts[t] += x; __syncthreads();
    }
    int pre = blockpre + ((t == 0) ? 0 : ts[t - 1]);
    #pragma unroll
    for (int j = 0; j < 4; j++) {
        int i = base + j;
        if (i < N_NODES) {
            g_off[i] = pre; g_cursor[i] = pre;
            g_dinv[i] = rsqrtf((float)v[j] + 1.0f);
        }
        pre += v[j];
    }
    if (blockIdx.x == 0 && t == 0) g_off[N_NODES] = N_EDGES;
}

// CSR fill: payload = {src row bits, norm = dinv[r]*dinv[c]}
__global__ void fill_kernel(const void* __restrict__ ei) {
    int e = blockIdx.x * blockDim.x + threadIdx.x;
    if (e >= N_EDGES) return;
    int r = load_ei(ei, e);
    int c = load_ei(ei, (long long)N_EDGES + e);
    int pos = atomicAdd(&g_cursor[c], 1);
    g_edge[pos] = make_float2(__int_as_float(r), g_dinv[r] * g_dinv[c]);
}

// ---------------------------------------------------------------------------
// GEMM: g_hh(half) = (relu? relu(A):A) @ W.  64-row tiles, 128 thr/block.
// ---------------------------------------------------------------------------
#define SA_STRIDE 66
__global__ __launch_bounds__(128) void gemm_kernel(const float* __restrict__ A,
                                                   const float* __restrict__ W,
                                                   int relu_in) {
    __shared__ float sA[64 * SA_STRIDE];
    __shared__ float sW[64 * 64];
    const int t = threadIdx.x;
    const int base = blockIdx.x * 64;

    for (int i = t; i < 1024; i += 128)
        ((float4*)sW)[i] = ((const float4*)W)[i];

    for (int i = t; i < 1024; i += 128) {
        int row = i >> 4, quad = i & 15;
        int gr = base + row;
        float4 v = make_float4(0.f, 0.f, 0.f, 0.f);
        if (gr < N_NODES) v = ((const float4*)A)[gr * 16 + quad];
        if (relu_in) {
            v.x = fmaxf(v.x, 0.f); v.y = fmaxf(v.y, 0.f);
            v.z = fmaxf(v.z, 0.f); v.w = fmaxf(v.w, 0.f);
        }
        float* dst = sA + row * SA_STRIDE + quad * 4;
        dst[0] = v.x; dst[1] = v.y; dst[2] = v.z; dst[3] = v.w;
    }
    __syncthreads();

    const int q2  = t & 7;
    const int grp = t >> 3;
    unsigned long long acc[4][4];
    #pragma unroll
    for (int r = 0; r < 4; r++)
        #pragma unroll
        for (int p = 0; p < 4; p++) acc[r][p] = 0ull;

    const float* wbase = sW + q2 * 8;
    const float* abase = sA + grp * 4 * SA_STRIDE;

    #pragma unroll 8
    for (int k = 0; k < 64; k++) {
        const float* wr = wbase + k * 64;
        unsigned long long w0 = *(const unsigned long long*)(wr + 0);
        unsigned long long w1 = *(const unsigned long long*)(wr + 2);
        unsigned long long w2 = *(const unsigned long long*)(wr + 4);
        unsigned long long w3 = *(const unsigned long long*)(wr + 6);
        #pragma unroll
        for (int r = 0; r < 4; r++) {
            unsigned long long a2 = dupf(abase[r * SA_STRIDE + k]);
            fma2(acc[r][0], a2, w0);
            fma2(acc[r][1], a2, w1);
            fma2(acc[r][2], a2, w2);
            fma2(acc[r][3], a2, w3);
        }
    }

    #pragma unroll
    for (int r = 0; r < 4; r++) {
        int gr = base + grp * 4 + r;
        if (gr >= N_NODES) continue;
        half2 h0 = __float22half2_rn(unpack2(acc[r][0]));
        half2 h1 = __float22half2_rn(unpack2(acc[r][1]));
        half2 h2 = __float22half2_rn(unpack2(acc[r][2]));
        half2 h3 = __float22half2_rn(unpack2(acc[r][3]));
        uint4 u;
        u.x = *(unsigned*)&h0; u.y = *(unsigned*)&h1;
        u.z = *(unsigned*)&h2; u.w = *(unsigned*)&h3;
        ((uint4*)g_hh)[gr * 8 + q2] = u;
    }
}

// ---------------------------------------------------------------------------
// CSR aggregation: 16 threads/node, fp16 gathers, unroll-4 for MLP.
// ---------------------------------------------------------------------------
__device__ __forceinline__ void acc4h(float* a, uint2 u, float n) {
    float2 f0 = __half22float2(*(half2*)&u.x);
    float2 f1 = __half22float2(*(half2*)&u.y);
    a[0] += f0.x * n; a[1] += f0.y * n;
    a[2] += f1.x * n; a[3] += f1.y * n;
}

__global__ __launch_bounds__(256) void agg_kernel(const float* __restrict__ bias,
                                                  const void* __restrict__ batch,
                                                  int to_pool) {
    int gid = blockIdx.x * blockDim.x + threadIdx.x;
    if (gid >= N_NODES * 16) return;
    int node = gid >> 4, q = gid & 15;
    int j   = g_off[node];
    int end = g_off[node + 1];
    const uint2* h = (const uint2*)g_hh;    // 16 uint2 per row

    float a[4] = {0.f, 0.f, 0.f, 0.f};
    for (; j + 4 <= end; j += 4) {
        float2 e0 = g_edge[j],     e1 = g_edge[j + 1];
        float2 e2 = g_edge[j + 2], e3 = g_edge[j + 3];
        uint2 u0 = h[(__float_as_int(e0.x) << 4) + q];
        uint2 u1 = h[(__float_as_int(e1.x) << 4) + q];
        uint2 u2 = h[(__float_as_int(e2.x) << 4) + q];
        uint2 u3 = h[(__float_as_int(e3.x) << 4) + q];
        acc4h(a, u0, e0.y);
        acc4h(a, u1, e1.y);
        acc4h(a, u2, e2.y);
        acc4h(a, u3, e3.y);
    }
    for (; j < end; j++) {
        float2 e0 = g_edge[j];
        acc4h(a, h[(__float_as_int(e0.x) << 4) + q], e0.y);
    }
    // self loop + bias
    float di = g_dinv[node];
    acc4h(a, h[(node << 4) + q], di * di);
    float4 b = ((const float4*)bias)[q];
    a[0] += b.x; a[1] += b.y; a[2] += b.z; a[3] += b.w;

    if (to_pool) {
        int bg = load_bat(batch, node);
        red_add_v4(&g_pool[bg * D + q * 4], make_float4(a[0], a[1], a[2], a[3]));
    } else {
        ((float4*)g_agg)[gid] = make_float4(a[0], a[1], a[2], a[3]);
    }
}

__global__ void final_kernel(const float* __restrict__ linW,
                             const float* __restrict__ linb,
                             float* __restrict__ out) {
    int id = blockIdx.x * blockDim.x + threadIdx.x;
    if (id >= N_GRAPHS * N_CLASSES) return;
    int b = id / N_CLASSES, c = id % N_CLASSES;
    int cnt = g_lb[b + 1] - g_lb[b];
    float inv = 1.0f / fmaxf((float)cnt, 1.0f);
    float acc = linb[c];
    #pragma unroll
    for (int d = 0; d < D; d++)
        acc += (g_pool[b * D + d] * inv) * linW[d * N_CLASSES + c];
    out[id] = acc;
}

extern "C" void kernel_launch(void* const* d_in, const int* in_sizes, int n_in,
                              void* d_out, int out_size) {
    const float* x    = (const float*)d_in[0];
    const void*  ei   = d_in[1];
    const void*  bat  = d_in[2];
    const float* W1   = (const float*)d_in[3];
    const float* b1   = (const float*)d_in[4];
    const float* W2   = (const float*)d_in[5];
    const float* b2   = (const float*)d_in[6];
    const float* W3   = (const float*)d_in[7];
    const float* b3   = (const float*)d_in[8];
    const float* linW = (const float*)d_in[9];
    const float* linb = (const float*)d_in[10];
    float* out = (float*)d_out;

    void *deg_p, *agg_p;
    cudaGetSymbolAddress(&deg_p, g_deg);
    cudaGetSymbolAddress(&agg_p, g_agg);
    const float* agg = (const float*)agg_p;

    cudaMemsetAsync(deg_p, 0, N_NODES * sizeof(int));

    detect_kernel<<<1, 256>>>((const int*)ei, (const int*)bat);
    deg_kernel<<<(N_EDGES + 255) / 256, 256>>>(ei);
    lb_kernel<<<(N_NODES + 255) / 256, 256>>>(bat);
    scan1_kernel<<<SCAN_NB, 256>>>();
    scan3_kernel<<<SCAN_NB, 256>>>();
    fill_kernel<<<(N_EDGES + 255) / 256, 256>>>(ei);

    const int GEMM_BLOCKS = (N_NODES + 63) / 64;
    const int NODE16      = (N_NODES * 16 + 255) / 256;

    gemm_kernel<<<GEMM_BLOCKS, 128>>>(x, W1, 0);
    agg_kernel<<<NODE16, 256>>>(b1, bat, 0);
    gemm_kernel<<<GEMM_BLOCKS, 128>>>(agg, W2, 1);
    agg_kernel<<<NODE16, 256>>>(b2, bat, 0);
    gemm_kernel<<<GEMM_BLOCKS, 128>>>(agg, W3, 1);
    agg_kernel<<<NODE16, 256>>>(b3, bat, 1);   // fused pool

    final_kernel<<<(N_GRAPHS * N_CLASSES + 255) / 256, 256>>>(linW, linb, out);
}